// round 7
// baseline (speedup 1.0000x reference)
#include <cuda_runtime.h>
#include <cstdint>

// ConvTranspose2d(64->64,k4,s2,p1)+bias+mish+(+0.5,clip,*2) via mma.sync tf32.
// y[p,oc] = sum_k A[p,k]*B[oc,k], k = (b*2+a)*64 + ic, K=256.
//   pixel p=(ohi,m): oh = ph+4t+2*ohi, ow = 2m+pw ; Rb = 2t+ph
//   A[p,k] = x[n, ic, Rb+ohi-a, m+pw-b]   (zero OOB)
//   B[oc,k] = w[oc, ic, (1-ph)+2a, (1-pw)+2b]
// CTA fixes (ph,pw): B = 64KB, xT = 195 rows x 256B (row=(r,c), ic-major,
// XOR bank swizzle) = 49920B -> 115.7KB SMEM -> 2 CTAs/SM, 32 warps/SM.
// 512 thr, 16 warps: warp = (ocg, mq), tile 32px x 16oc, acc 16 regs.
// Persistent: 296 CTAs, classes (ph,pw), 74 slots x ~27.7 tiles (n,t).

#define NT 512
#define SM_BIAS 0
#define SM_B    256
#define SM_XT   (SM_B + 65536)          // 65792, 256B aligned
#define SMEM_TOTAL (SM_XT + 195 * 256)  // 115712

static __device__ __forceinline__ uint32_t s2u(const void* p) {
    uint32_t a;
    asm("{ .reg .u64 t; cvta.to.shared.u64 t, %1; cvt.u32.u64 %0, t; }" : "=r"(a) : "l"(p));
    return a;
}
static __device__ __forceinline__ uint32_t cvt_tf32(float f) {
    uint32_t r; asm("cvt.rn.tf32.f32 %0, %1;" : "=r"(r) : "f"(f)); return r;
}
static __device__ __forceinline__ void sts32(uint32_t addr, uint32_t v) {
    asm volatile("st.shared.b32 [%0], %1;" :: "r"(addr), "r"(v) : "memory");
}
static __device__ __forceinline__ void ldsm4(uint32_t* r, uint32_t addr) {
    asm volatile("ldmatrix.sync.aligned.m8n8.x4.shared.b16 {%0,%1,%2,%3}, [%4];"
                 : "=r"(r[0]), "=r"(r[1]), "=r"(r[2]), "=r"(r[3]) : "r"(addr));
}
static __device__ __forceinline__ void mma8(float* d, const uint32_t* a,
                                            uint32_t b0, uint32_t b1) {
    asm volatile("mma.sync.aligned.m16n8k8.row.col.f32.tf32.tf32.f32 "
                 "{%0,%1,%2,%3}, {%4,%5,%6,%7}, {%8,%9}, {%0,%1,%2,%3};"
                 : "+f"(d[0]), "+f"(d[1]), "+f"(d[2]), "+f"(d[3])
                 : "r"(a[0]), "r"(a[1]), "r"(a[2]), "r"(a[3]), "r"(b0), "r"(b1));
}

__device__ __forceinline__ float postop(float y) {
    // mish(y) = y*(t^2+2t)/(t^2+2t+2), t=e^y ; then +0.5, clip[-1,1], *2
    float t = __expf(fminf(y, 30.0f));
    float u = t * (t + 2.0f);
    float mish = y * __fdividef(u, u + 2.0f);
    float v = fminf(fmaxf(mish + 0.5f, -1.0f), 1.0f);
    return v * 2.0f;
}

__global__ __launch_bounds__(NT, 2)
void convt_mma_kernel(const float* __restrict__ x,
                      const float* __restrict__ weight,
                      const float* __restrict__ bias,
                      float* __restrict__ out) {
    extern __shared__ char smem[];
    const uint32_t sb = s2u(smem);
    const int tid  = threadIdx.x;
    const int warp = tid >> 5;
    const int lane = tid & 31;
    const int ph   = blockIdx.x & 1;
    const int pw   = (blockIdx.x >> 1) & 1;
    const int slot = blockIdx.x >> 2;     // 0..73

    if (tid < 64) ((float*)smem)[tid] = bias[tid];

    // ---- stage B once: B[oc][k] tf32, row 1024B, byte = k*4 ^ ((oc&7)<<4) ----
    for (int it = 0; it < 32; it++) {
        int idx = tid + it * NT;          // 0..16383
        int oc = idx >> 8;
        int k  = idx & 255;
        int g = k >> 6, ic = k & 63, a = g & 1, b = g >> 1;
        int kh = (1 - ph) + 2 * a;
        int kw = (1 - pw) + 2 * b;
        float f = __ldg(weight + ((oc * 64 + ic) << 4) + (kh << 2) + kw);
        uint32_t byte = ((uint32_t)(k << 2)) ^ ((uint32_t)(oc & 7) << 4);
        sts32(sb + SM_B + oc * 1024 + byte, cvt_tf32(f));
    }
    __syncthreads();

    // warp roles: ocg (0..3) | mq (0..3)
    const int mq  = warp & 3;
    const int ocg = warp >> 2;
    const int p0  = 32 * mq;              // pixel base (p = ohi*64 + m)
    const int ohi = mq >> 1;
    const int msub0 = 32 * (mq & 1);

    // per-lane LDSM indices
    const int l15 = lane & 15;
    const int lhi = lane >> 4;
    const int oc_l = (lane & 7) + 8 * lhi;
    const uint32_t khalf = (uint32_t)((lane >> 3) & 1) << 4;
    const uint32_t swzB  = (uint32_t)(lane & 7) << 4;
    const uint32_t rbB   = sb + SM_B + (uint32_t)(16 * ocg + oc_l) * 1024;

    for (int widx = slot; widx < 2048; widx += 74) {
        const int n = widx >> 5;
        const int t = widx & 31;
        const int Rb = 2 * t + ph;
        const float* xn = x + (size_t)n * (64 * 64 * 64);

        // ---- stage xT: row=(r*65+c) 0..194, 256B of ic; byte = ic*4 ^ ((row&7)<<5)
        //      value = x[n, ic, Rb-1+r, (c-1)+pw], zero OOB ----
#pragma unroll 1
        for (int it = 0; it < 25; it++) {
            int idx = tid + it * NT;
            if (idx < 12480) {                 // 192*65
                int rr = idx / 65;
                int c  = idx - rr * 65;
                int r  = rr >> 6;              // 0..2
                int ic = rr & 63;
                int rg = Rb - 1 + r;
                int j  = c - 1 + pw;
                float v = 0.0f;
                if ((unsigned)rg < 64u && (unsigned)j < 64u)
                    v = __ldg(xn + (ic * 64 + rg) * 64 + j);
                int row = r * 65 + c;
                uint32_t byte = ((uint32_t)(ic << 2)) ^ ((uint32_t)(row & 7) << 5);
                sts32(sb + SM_XT + row * 256 + byte, cvt_tf32(v));
            }
        }
        __syncthreads();

        float acc[2][2][4];
#pragma unroll
        for (int i = 0; i < 2; i++)
#pragma unroll
            for (int j = 0; j < 2; j++)
#pragma unroll
                for (int e = 0; e < 4; e++) acc[i][j][e] = 0.0f;

#pragma unroll 1
        for (int g = 0; g < 4; g++) {
            const int a = g & 1, b = g >> 1;
            const int rowsel  = ohi + 1 - a;
            const int colbase = msub0 + 1 - b;
            const int rowL = rowsel * 65 + colbase + l15;
            const uint32_t r7 = (uint32_t)(rowL & 7);
            const uint32_t abase = sb + SM_XT + (uint32_t)rowL * 256 + ((uint32_t)lhi << 4);
            const uint32_t kb0 = ((uint32_t)g << 8) + khalf;

#pragma unroll
            for (int s8 = 0; s8 < 8; s8++) {
                const uint32_t koff = ((uint32_t)s8 ^ r7) << 5;
                uint32_t Af0[4], Af1[4];
                ldsm4(Af0, abase + koff);
                ldsm4(Af1, abase + 4096 + koff);
                uint32_t Bf[4];
                ldsm4(Bf, rbB + ((kb0 + ((uint32_t)s8 << 5)) ^ swzB));
                mma8(acc[0][0], Af0, Bf[0], Bf[1]);
                mma8(acc[0][1], Af0, Bf[2], Bf[3]);
                mma8(acc[1][0], Af1, Bf[0], Bf[1]);
                mma8(acc[1][1], Af1, Bf[2], Bf[3]);
            }
        }
        __syncthreads();   // xT dead; region becomes ys

        // ---- epilogue: postop -> ys[oc][132-padded p] in xT region ----
        float* ysf = (float*)(smem + SM_XT);
        const float* bsm = (const float*)smem;
        const int gL = lane >> 2, tg = lane & 3;
#pragma unroll
        for (int i = 0; i < 2; i++) {
            const int prow = p0 + 16 * i + gL;
#pragma unroll
            for (int j = 0; j < 2; j++) {
                const int oc = 16 * ocg + 8 * j + 2 * tg;
                const float b0v = bsm[oc], b1v = bsm[oc + 1];
                const int base = oc * 132;
                ysf[base + prow]           = postop(acc[i][j][0] + b0v);
                ysf[base + 132 + prow]     = postop(acc[i][j][1] + b1v);
                ysf[base + prow + 8]       = postop(acc[i][j][2] + b0v);
                ysf[base + 132 + prow + 8] = postop(acc[i][j][3] + b1v);
            }
        }
        __syncthreads();

        // ---- store: 8192 scalar STG (ow stride 2) ----
        float* ob = out + (size_t)n * 64 * 16384 + (size_t)(ph + 4 * t) * 128 + pw;
#pragma unroll
        for (int it = 0; it < 16; it++) {
            int vid = tid + it * NT;
            int oc  = vid >> 7;
            int p   = vid & 127;
            int oh2 = p >> 6;
            int m   = p & 63;
            ob[(size_t)oc * 16384 + oh2 * 256 + 2 * m] = ysf[oc * 132 + p];
        }
        __syncthreads();   // ys dead before next tile's xT staging
    }
}

extern "C" void kernel_launch(void* const* d_in, const int* in_sizes, int n_in,
                              void* d_out, int out_size) {
    const float* x      = (const float*)d_in[0];
    const float* weight = (const float*)d_in[1];
    const float* bias   = (const float*)d_in[2];
    float* out          = (float*)d_out;

    cudaFuncSetAttribute(convt_mma_kernel,
                         cudaFuncAttributeMaxDynamicSharedMemorySize, SMEM_TOTAL);
    convt_mma_kernel<<<296, NT, SMEM_TOTAL>>>(x, weight, bias, out);
}